// round 15
// baseline (speedup 1.0000x reference)
#include <cuda_runtime.h>
#include <cuda_fp16.h>
#include <math.h>
#include <stdint.h>

// ----------------------------------------------------------------------------
// DYS_opt_net.  ALL GEMMs on legacy fp16 mma.sync m16n8k16 with fp16x3 split
// (hh+hl+lh, fp32 accum), static per-matrix scaling, symmetrized Newton-Schulz.
// R15: loop GEMM1 operand-swapped (outputs r^T directly, no transpose) and both
// loop reductions+epilogues fused into the GEMM tails via last-CTA-per-tile
// ticket reduction (deterministic fixed-order partial sum). 2 kernels/iter.
// z' = relu(z) - a*w + c - (G (A u^T))^T,  u = |z| - a*w
// ----------------------------------------------------------------------------

#define N1C 1024
#define N2C 4096
#define BC  256
#define DC  512
#define HC  2048

#define ALPHA_C 0.05f
#define EPS_C   0.01f
#define NS_ITERS 6
#define NS_CHEAP 4
#define PI_ITERS 12

#define A_SC 64.f
#define G_SC 32.f
#define INV_A_SC 0.015625f
#define INV_G_SC 0.03125f

#define SPL_GR 16
#define SPL_GZ 4
#define SPL_S  4
#define SPL_NS 4
#define SPL_M1 8
#define SPL_M2 4

#define EPI_NONE 0
#define EPI_RT   1
#define EPI_Z    2
#define EPI_ZFIN 3

// fp16 GEMM tile config
#define HBK 32
#define HSTR 40
#define HPL (128*HSTR)
#define HST (4*HPL)
#define HSMEM (2*HST*2)          // 81920 B -> 2 CTAs/SM

__device__ float g_S  [(size_t)N1C*N1C];
__device__ float g_Xa [(size_t)N1C*N1C];
__device__ float g_Xb [(size_t)N1C*N1C];
__device__ float g_T  [(size_t)N1C*N1C];
__device__ float g_G  [(size_t)N2C*N1C];
__device__ float g_At [(size_t)N2C*N1C];
__device__ float g_W1t[(size_t)HC*DC];
__device__ float g_W2t[(size_t)N2C*HC];
__device__ float g_c  [N2C];
__device__ float g_tv [N1C];
__device__ float g_v  [N1C];
__device__ float g_y  [N1C];
__device__ float g_h  [(size_t)BC*HC];
__device__ float g_w  [(size_t)BC*N2C];
__device__ float g_za [(size_t)BC*N2C];
__device__ float g_zb [(size_t)BC*N2C];
__device__ float g_P  [(size_t)4*1024*1024];
__device__ __half g_Ah [(size_t)N1C*N2C];
__device__ __half g_Al [(size_t)N1C*N2C];
__device__ __half g_Gh [(size_t)N2C*N1C];
__device__ __half g_Gl [(size_t)N2C*N1C];
__device__ __half g_uh [(size_t)BC*N2C];
__device__ __half g_ul [(size_t)BC*N2C];
__device__ __half g_rth[(size_t)BC*N1C];
__device__ __half g_rtl[(size_t)BC*N1C];
__device__ __half g_Sh [(size_t)N1C*N1C];
__device__ __half g_Sl [(size_t)N1C*N1C];
__device__ __half g_Xh [(size_t)N1C*N1C];
__device__ __half g_Xl [(size_t)N1C*N1C];
__device__ __half g_Th [(size_t)N1C*N1C];
__device__ __half g_Tl [(size_t)N1C*N1C];
__device__ __half g_dh [(size_t)BC*DC];
__device__ __half g_dl [(size_t)BC*DC];
__device__ __half g_W1h[(size_t)HC*DC];
__device__ __half g_W1l[(size_t)HC*DC];
__device__ __half g_W2h[(size_t)N2C*HC];
__device__ __half g_W2l[(size_t)N2C*HC];
__device__ __half g_hph[(size_t)BC*HC];
__device__ __half g_hpl[(size_t)BC*HC];
__device__ float g_lam;
__device__ float g_ss;
__device__ int   g_flag;
__device__ int   g_cnt;
__device__ int   g_tk[64];

// ---------------- small utility kernels ----------------
__global__ void init_k() {
    g_ss = 0.f; g_flag = 0; g_cnt = 0;
    for (int i = 0; i < 64; i++) g_tk[i] = 0;
}

__global__ void copy4_k(float4* __restrict__ dst, const float4* __restrict__ src) {
    int i = blockIdx.x * blockDim.x + threadIdx.x;
    dst[i] = src[i];
}

__global__ void fill_k(float* v, float val, int n) {
    int i = blockIdx.x * blockDim.x + threadIdx.x;
    if (i < n) v[i] = val;
}

__global__ void symm_k(float* __restrict__ X) {
    int j = blockIdx.x * 32 + (threadIdx.x & 31);
    int i = blockIdx.y * 8 + (threadIdx.x >> 5);
    if (i < j) {
        size_t ij = (size_t)i * N1C + j;
        size_t ji = (size_t)j * N1C + i;
        float m = 0.5f * (X[ij] + X[ji]);
        X[ij] = m;
        X[ji] = m;
    }
}

__global__ void spmv_k(const float* __restrict__ M_, const float* __restrict__ v,
                       float* __restrict__ y) {
    int row = blockIdx.x * 8 + threadIdx.y;
    const float* mr = M_ + (size_t)row * N1C;
    float s = 0.f;
    for (int j = threadIdx.x; j < N1C; j += 32) s += mr[j] * v[j];
    #pragma unroll
    for (int o = 16; o; o >>= 1) s += __shfl_xor_sync(0xffffffffu, s, o);
    if (threadIdx.x == 0) y[row] = s;
}

__global__ void pi_norm_k(const float* __restrict__ y, float* __restrict__ v) {
    __shared__ float red[256];
    float s = 0.f;
    for (int i = threadIdx.x; i < N1C; i += 256) { float t = y[i]; s += t * t; }
    red[threadIdx.x] = s; __syncthreads();
    for (int o = 128; o; o >>= 1) {
        if (threadIdx.x < o) red[threadIdx.x] += red[threadIdx.x + o];
        __syncthreads();
    }
    float nrm = sqrtf(red[0]);
    float inv = 1.f / nrm;
    for (int i = threadIdx.x; i < N1C; i += 256) v[i] = y[i] * inv;
    if (threadIdx.x == 0) g_lam = nrm;
}

__global__ void initX_k(float* X) {
    float a = 1.8f / g_lam;
    int i = blockIdx.x * 256 + threadIdx.x;
    int rr = i / N1C, cc = i % N1C;
    X[i] = (rr == cc) ? a : 0.f;
}

__global__ void atmv_k(const float* __restrict__ A, const float* __restrict__ t,
                       float* __restrict__ c) {
    __shared__ float ts[N1C];
    for (int i = threadIdx.x; i < N1C; i += 256) ts[i] = t[i];
    __syncthreads();
    int j = blockIdx.x * 256 + threadIdx.x;
    float s = 0.f;
    for (int i = 0; i < N1C; i++) s += A[(size_t)i * N2C + j] * ts[i];
    c[j] = s;
}

__global__ void transp_k(float* __restrict__ dst, const float* __restrict__ src,
                         int R, int C) {
    __shared__ float t[32][33];
    int bx = blockIdx.x * 32, by = blockIdx.y * 32;
    #pragma unroll
    for (int i = 0; i < 4; i++) {
        int r = by + threadIdx.y + i * 8;
        t[threadIdx.y + i * 8][threadIdx.x] = src[(size_t)r * C + bx + threadIdx.x];
    }
    __syncthreads();
    #pragma unroll
    for (int i = 0; i < 4; i++) {
        int r = bx + threadIdx.y + i * 8;
        dst[(size_t)r * R + by + threadIdx.x] = t[threadIdx.x][threadIdx.y + i * 8];
    }
}

__device__ __forceinline__ void split2h(float x, __half& h, __half& l) {
    h = __float2half_rn(x);
    l = __float2half_rn(x - __half2float(h));
}

__global__ void splitH_k(const float* __restrict__ src, __half* __restrict__ ph,
                         __half* __restrict__ pl, float scale) {
    size_t e = ((size_t)blockIdx.x * 256 + threadIdx.x) * 8;
    uint32_t hh[4], ll[4];
    #pragma unroll
    for (int p = 0; p < 4; p++) {
        __half h0, h1, l0, l1;
        split2h(src[e + 2 * p] * scale, h0, l0);
        split2h(src[e + 2 * p + 1] * scale, h1, l1);
        __half2 hp = __halves2half2(h0, h1), lp = __halves2half2(l0, l1);
        hh[p] = *(uint32_t*)&hp; ll[p] = *(uint32_t*)&lp;
    }
    *(uint4*)(ph + e) = make_uint4(hh[0], hh[1], hh[2], hh[3]);
    *(uint4*)(pl + e) = make_uint4(ll[0], ll[1], ll[2], ll[3]);
}

__global__ void u0_k(const float* __restrict__ z, const float* __restrict__ w) {
    size_t i = (size_t)blockIdx.x * 256 + threadIdx.x;
    float4 zv = ((const float4*)z)[i];
    float4 wv = ((const float4*)w)[i];
    __half h0, h1, h2, h3, l0, l1, l2, l3;
    split2h(fabsf(zv.x) - ALPHA_C * wv.x, h0, l0);
    split2h(fabsf(zv.y) - ALPHA_C * wv.y, h1, l1);
    split2h(fabsf(zv.z) - ALPHA_C * wv.z, h2, l2);
    split2h(fabsf(zv.w) - ALPHA_C * wv.w, h3, l3);
    __half2 ha = __halves2half2(h0, h1), hb = __halves2half2(h2, h3);
    __half2 la = __halves2half2(l0, l1), lb = __halves2half2(l2, l3);
    ((uint2*)g_uh)[i] = make_uint2(*(uint32_t*)&ha, *(uint32_t*)&hb);
    ((uint2*)g_ul)[i] = make_uint2(*(uint32_t*)&la, *(uint32_t*)&lb);
}

// ---------------- reduce kernels for precompute ----------------
__global__ void reduce_sum_k(const float* __restrict__ P, float* __restrict__ out,
                             size_t stride4, int ns, float scale) {
    size_t i = ((size_t)blockIdx.x * 256 + threadIdx.x) * 2;
    const float4* p = (const float4*)P;
    float4 s0 = p[i], s1 = p[i + 1];
    for (int sp = 1; sp < ns; sp++) {
        float4 t0 = p[(size_t)sp * stride4 + i];
        float4 t1 = p[(size_t)sp * stride4 + i + 1];
        s0.x += t0.x; s0.y += t0.y; s0.z += t0.z; s0.w += t0.w;
        s1.x += t1.x; s1.y += t1.y; s1.z += t1.z; s1.w += t1.w;
    }
    s0.x *= scale; s0.y *= scale; s0.z *= scale; s0.w *= scale;
    s1.x *= scale; s1.y *= scale; s1.z *= scale; s1.w *= scale;
    ((float4*)out)[i] = s0;
    ((float4*)out)[i + 1] = s1;
}

__global__ void reduce_ns_k(const float* __restrict__ P, const float* __restrict__ X,
                            float* __restrict__ out, size_t stride4, int ns, float scale) {
    size_t i = ((size_t)blockIdx.x * 256 + threadIdx.x) * 2;
    const float4* p = (const float4*)P;
    float4 s0 = p[i], s1 = p[i + 1];
    for (int sp = 1; sp < ns; sp++) {
        float4 t0 = p[(size_t)sp * stride4 + i];
        float4 t1 = p[(size_t)sp * stride4 + i + 1];
        s0.x += t0.x; s0.y += t0.y; s0.z += t0.z; s0.w += t0.w;
        s1.x += t1.x; s1.y += t1.y; s1.z += t1.z; s1.w += t1.w;
    }
    float4 x0 = ((const float4*)X)[i], x1 = ((const float4*)X)[i + 1];
    float4 o0, o1;
    o0.x = 2.f * x0.x - s0.x * scale; o0.y = 2.f * x0.y - s0.y * scale;
    o0.z = 2.f * x0.z - s0.z * scale; o0.w = 2.f * x0.w - s0.w * scale;
    o1.x = 2.f * x1.x - s1.x * scale; o1.y = 2.f * x1.y - s1.y * scale;
    o1.z = 2.f * x1.z - s1.z * scale; o1.w = 2.f * x1.w - s1.w * scale;
    ((float4*)out)[i] = o0;
    ((float4*)out)[i + 1] = o1;
}

template<bool RELU>
__global__ void reduce_bias_k(const float* __restrict__ P, const float* __restrict__ bias,
                              float* __restrict__ out, size_t stride4, int ns, int n4,
                              float scale) {
    size_t i = ((size_t)blockIdx.x * 256 + threadIdx.x) * 2;
    const float4* p = (const float4*)P;
    float4 s0 = p[i], s1 = p[i + 1];
    for (int sp = 1; sp < ns; sp++) {
        float4 t0 = p[(size_t)sp * stride4 + i];
        float4 t1 = p[(size_t)sp * stride4 + i + 1];
        s0.x += t0.x; s0.y += t0.y; s0.z += t0.z; s0.w += t0.w;
        s1.x += t1.x; s1.y += t1.y; s1.z += t1.z; s1.w += t1.w;
    }
    float4 b0 = ((const float4*)bias)[i % n4];
    float4 b1 = ((const float4*)bias)[(i + 1) % n4];
    s0.x = s0.x * scale + b0.x; s0.y = s0.y * scale + b0.y;
    s0.z = s0.z * scale + b0.z; s0.w = s0.w * scale + b0.w;
    s1.x = s1.x * scale + b1.x; s1.y = s1.y * scale + b1.y;
    s1.z = s1.z * scale + b1.z; s1.w = s1.w * scale + b1.w;
    if (RELU) {
        s0.x = fmaxf(s0.x, 0.f); s0.y = fmaxf(s0.y, 0.f);
        s0.z = fmaxf(s0.z, 0.f); s0.w = fmaxf(s0.w, 0.f);
        s1.x = fmaxf(s1.x, 0.f); s1.y = fmaxf(s1.y, 0.f);
        s1.z = fmaxf(s1.z, 0.f); s1.w = fmaxf(s1.w, 0.f);
    }
    ((float4*)out)[i] = s0;
    ((float4*)out)[i + 1] = s1;
}

// ---------------- fp16 GEMM with fused tail reductions ----------------
__device__ __forceinline__ uint32_t smem_u32(const void* p) {
    uint32_t a;
    asm("{ .reg .u64 t; cvta.to.shared.u64 t, %1; cvt.u32.u64 %0, t; }" : "=r"(a) : "l"(p));
    return a;
}
__device__ __forceinline__ void cp16(uint32_t dst, const void* src) {
    asm volatile("cp.async.cg.shared.global [%0], [%1], 16;" :: "r"(dst), "l"(src));
}
__device__ __forceinline__ void ldsm4(uint32_t* r, uint32_t a) {
    asm volatile("ldmatrix.sync.aligned.m8n8.x4.shared.b16 {%0,%1,%2,%3}, [%4];"
        : "=r"(r[0]), "=r"(r[1]), "=r"(r[2]), "=r"(r[3]) : "r"(a));
}
__device__ __forceinline__ void mma16(float* c, const uint32_t* a, const uint32_t* b) {
    asm volatile("mma.sync.aligned.m16n8k16.row.col.f32.f16.f16.f32 "
        "{%0,%1,%2,%3}, {%4,%5,%6,%7}, {%8,%9}, {%0,%1,%2,%3};"
        : "+f"(c[0]), "+f"(c[1]), "+f"(c[2]), "+f"(c[3])
        : "r"(a[0]), "r"(a[1]), "r"(a[2]), "r"(a[3]), "r"(b[0]), "r"(b[1]));
}

template<int NP, int EPI>
__global__ void __launch_bounds__(256, 2)
hgemm_k(const __half* __restrict__ Ahp, const __half* __restrict__ Alp, int lda,
        const __half* __restrict__ Bhp, const __half* __restrict__ Blp, int ldb,
        float* __restrict__ Cg, int N, int kchunk, const int* __restrict__ guard,
        const float* __restrict__ zin, const float* __restrict__ wv,
        const float* __restrict__ cv, float* __restrict__ zout)
{
    extern __shared__ __half hsm[];
    const int tid = threadIdx.x, lane = tid & 31, wid = tid >> 5;
    const int wm = wid >> 2, wn = wid & 3;
    const int m0 = blockIdx.y * 128, n0 = blockIdx.x * 128;

    if (guard && *guard) {
        if (EPI == EPI_Z && blockIdx.z == 0) {
            #pragma unroll
            for (int e = 0; e < 16; e++) {
                int idx = e * 256 + tid;
                int r = idx >> 5, c4 = idx & 31;
                size_t ad4 = ((size_t)(m0 + r) * N + n0) / 4 + c4;
                ((float4*)zout)[ad4] = ((const float4*)zin)[ad4];
            }
        }
        return;
    }

    const int k0 = blockIdx.z * kchunk;
    const int ST = kchunk / HBK;
    const __half* psrc[4] = { Ahp, Alp, Bhp, Blp };
    uint32_t sbase = smem_u32(hsm);

    auto load = [&](int s) {
        int buf = s & 1;
        int kb = k0 + s * HBK;
        #pragma unroll
        for (int t = 0; t < (NP == 3 ? 8 : 4); t++) {
            int id = t * 256 + tid;
            int pl = (NP == 3) ? (id >> 9) : ((id >> 9) * 2);
            int idx = id & 511;
            int row = idx >> 2, kc = idx & 3;
            int isB = pl >> 1;
            const __half* src = psrc[pl] +
                (size_t)((isB ? n0 : m0) + row) * (isB ? ldb : lda) + kb + kc * 8;
            uint32_t dst = sbase + (uint32_t)(buf * HST + pl * HPL + row * HSTR + kc * 8) * 2;
            cp16(dst, src);
        }
    };

    float acc[4][4][4];
    #pragma unroll
    for (int f = 0; f < 4; f++)
        #pragma unroll
        for (int g = 0; g < 4; g++)
            #pragma unroll
            for (int e = 0; e < 4; e++) acc[f][g][e] = 0.f;

    load(0);
    asm volatile("cp.async.commit_group;");
    load(1);
    asm volatile("cp.async.commit_group;");

    const int offA = (lane & 15) * HSTR + (lane >> 4) * 8;
    const int offB = ((lane & 7) + ((lane >> 4) << 3)) * HSTR + ((lane >> 3) & 1) * 8;

    for (int s = 0; s < ST; s++) {
        asm volatile("cp.async.wait_group 1;");
        __syncthreads();
        uint32_t stg = sbase + (uint32_t)((s & 1) * HST) * 2;
        #pragma unroll
        for (int ks = 0; ks < 2; ks++) {
            uint32_t bH[4][2], bL[4][2];
            #pragma unroll
            for (int gp = 0; gp < 2; gp++) {
                uint32_t r[4];
                uint32_t base = stg + (uint32_t)(2 * HPL + (wn * 32 + gp * 16) * HSTR + ks * 16 + offB) * 2;
                ldsm4(r, base);
                bH[gp * 2][0] = r[0]; bH[gp * 2][1] = r[1];
                bH[gp * 2 + 1][0] = r[2]; bH[gp * 2 + 1][1] = r[3];
                if (NP == 3) {
                    ldsm4(r, base + HPL * 2);
                    bL[gp * 2][0] = r[0]; bL[gp * 2][1] = r[1];
                    bL[gp * 2 + 1][0] = r[2]; bL[gp * 2 + 1][1] = r[3];
                }
            }
            #pragma unroll
            for (int f = 0; f < 4; f++) {
                uint32_t aH[4], aL[4];
                uint32_t base = stg + (uint32_t)((wm * 64 + f * 16) * HSTR + ks * 16 + offA) * 2;
                ldsm4(aH, base);
                if (NP == 3) ldsm4(aL, base + HPL * 2);
                #pragma unroll
                for (int g = 0; g < 4; g++)
                    mma16(acc[f][g], aH, bH[g]);
                if (NP == 3) {
                    #pragma unroll
                    for (int g = 0; g < 4; g++)
                        mma16(acc[f][g], aH, bL[g]);
                    #pragma unroll
                    for (int g = 0; g < 4; g++)
                        mma16(acc[f][g], aL, bH[g]);
                }
            }
        }
        __syncthreads();
        if (s + 2 < ST) load(s + 2);
        asm volatile("cp.async.commit_group;");
    }

    size_t off = (size_t)blockIdx.z * ((size_t)gridDim.y * 128) * N;
    const int tr = lane >> 2, tc = (lane & 3) * 2;
    #pragma unroll
    for (int f = 0; f < 4; f++) {
        int m = m0 + wm * 64 + f * 16 + tr;
        #pragma unroll
        for (int g = 0; g < 4; g++) {
            int n = n0 + wn * 32 + g * 8 + tc;
            *(float2*)&Cg[off + (size_t)m * N + n] = make_float2(acc[f][g][0], acc[f][g][1]);
            *(float2*)&Cg[off + (size_t)(m + 8) * N + n] = make_float2(acc[f][g][2], acc[f][g][3]);
        }
    }

    if (EPI == EPI_NONE) return;

    // -------- last-CTA-per-tile fused reduction --------
    __threadfence();
    __syncthreads();
    __shared__ int amLast;
    const int tileId = blockIdx.y * gridDim.x + blockIdx.x;
    if (tid == 0) {
        int t = atomicAdd(&g_tk[tileId], 1);
        amLast = (t == (int)gridDim.z - 1);
    }
    __syncthreads();
    if (!amLast) return;
    if (tid == 0) g_tk[tileId] = 0;

    const size_t stride4 = (size_t)gridDim.y * 128 * (N / 4);
    const int NSP = (EPI == EPI_RT) ? SPL_GR : SPL_GZ;
    float ls = 0.f;
    #pragma unroll 4
    for (int e = 0; e < 16; e++) {
        int idx = e * 256 + tid;
        int r = idx >> 5, c4 = idx & 31;
        size_t ad4 = ((size_t)(m0 + r) * N + n0) / 4 + c4;
        float4 s = ((const float4*)Cg)[ad4];
        for (int sp = 1; sp < NSP; sp++) {
            float4 t = ((const float4*)Cg)[(size_t)sp * stride4 + ad4];
            s.x += t.x; s.y += t.y; s.z += t.z; s.w += t.w;
        }
        if (EPI == EPI_RT) {
            s.x *= INV_A_SC; s.y *= INV_A_SC; s.z *= INV_A_SC; s.w *= INV_A_SC;
            __half h0, h1, h2, h3, l0, l1, l2, l3;
            split2h(s.x, h0, l0); split2h(s.y, h1, l1);
            split2h(s.z, h2, l2); split2h(s.w, h3, l3);
            __half2 ha = __halves2half2(h0, h1), hb = __halves2half2(h2, h3);
            __half2 la = __halves2half2(l0, l1), lb = __halves2half2(l2, l3);
            size_t o = (size_t)(m0 + r) * N1C + n0 + c4 * 4;
            *(uint2*)(g_rth + o) = make_uint2(*(uint32_t*)&ha, *(uint32_t*)&hb);
            *(uint2*)(g_rtl + o) = make_uint2(*(uint32_t*)&la, *(uint32_t*)&lb);
        } else {
            float4 z = ((const float4*)zin)[ad4];
            float4 ww = ((const float4*)wv)[ad4];
            float4 cc = ((const float4*)cv)[(n0 >> 2) + c4];
            float4 o;
            o.x = fmaxf(z.x, 0.f) - ALPHA_C * ww.x + cc.x - s.x * INV_G_SC;
            o.y = fmaxf(z.y, 0.f) - ALPHA_C * ww.y + cc.y - s.y * INV_G_SC;
            o.z = fmaxf(z.z, 0.f) - ALPHA_C * ww.z + cc.z - s.z * INV_G_SC;
            o.w = fmaxf(z.w, 0.f) - ALPHA_C * ww.w + cc.w - s.w * INV_G_SC;
            if (EPI == EPI_ZFIN) {
                o.x = fmaxf(o.x, 0.f); o.y = fmaxf(o.y, 0.f);
                o.z = fmaxf(o.z, 0.f); o.w = fmaxf(o.w, 0.f);
                ((float4*)zout)[ad4] = o;
            } else {
                ((float4*)zout)[ad4] = o;
                float dx = o.x - z.x, dy = o.y - z.y, dz = o.z - z.z, dw = o.w - z.w;
                ls += dx * dx + dy * dy + dz * dz + dw * dw;
                __half h0, h1, h2, h3, l0, l1, l2, l3;
                split2h(fabsf(o.x) - ALPHA_C * ww.x, h0, l0);
                split2h(fabsf(o.y) - ALPHA_C * ww.y, h1, l1);
                split2h(fabsf(o.z) - ALPHA_C * ww.z, h2, l2);
                split2h(fabsf(o.w) - ALPHA_C * ww.w, h3, l3);
                __half2 ha = __halves2half2(h0, h1), hb = __halves2half2(h2, h3);
                __half2 la = __halves2half2(l0, l1), lb = __halves2half2(l2, l3);
                size_t oo = (size_t)(m0 + r) * N2C + n0 + c4 * 4;
                *(uint2*)(g_uh + oo) = make_uint2(*(uint32_t*)&ha, *(uint32_t*)&hb);
                *(uint2*)(g_ul + oo) = make_uint2(*(uint32_t*)&la, *(uint32_t*)&lb);
            }
        }
    }
    if (EPI == EPI_Z) {
        __shared__ float red[256];
        red[tid] = ls;
        __syncthreads();
        for (int o2 = 128; o2; o2 >>= 1) {
            if (tid < o2) red[tid] += red[tid + o2];
            __syncthreads();
        }
        if (tid == 0) {
            atomicAdd(&g_ss, red[0]);
            __threadfence();
            int t = atomicAdd(&g_cnt, 1);
            if (t == (int)(gridDim.x * gridDim.y) - 1) {
                if (g_ss <= EPS_C * EPS_C) g_flag = 1;
                g_ss = 0.f;
                g_cnt = 0;
            }
        }
    }
}

// ---------------- host ----------------
extern "C" void kernel_launch(void* const* d_in, const int* in_sizes, int n_in,
                              void* d_out, int out_size) {
    (void)in_sizes; (void)n_in; (void)out_size;
    const float* dd  = (const float*)d_in[0];
    const float* dA  = (const float*)d_in[1];
    const float* dB  = (const float*)d_in[2];
    const float* dW1 = (const float*)d_in[3];
    const float* db1 = (const float*)d_in[4];
    const float* dW2 = (const float*)d_in[5];
    const float* db2 = (const float*)d_in[6];
    const float* dz0 = (const float*)d_in[7];
    float* out = (float*)d_out;

    void* p;
    cudaGetSymbolAddress(&p, g_S);   float* S    = (float*)p;
    cudaGetSymbolAddress(&p, g_Xa);  float* Xa   = (float*)p;
    cudaGetSymbolAddress(&p, g_Xb);  float* Xb   = (float*)p;
    cudaGetSymbolAddress(&p, g_T);   float* Tm   = (float*)p;
    cudaGetSymbolAddress(&p, g_G);   float* G    = (float*)p;
    cudaGetSymbolAddress(&p, g_At);  float* At   = (float*)p;
    cudaGetSymbolAddress(&p, g_W1t); float* W1t  = (float*)p;
    cudaGetSymbolAddress(&p, g_W2t); float* W2t  = (float*)p;
    cudaGetSymbolAddress(&p, g_c);   float* c    = (float*)p;
    cudaGetSymbolAddress(&p, g_tv);  float* tv   = (float*)p;
    cudaGetSymbolAddress(&p, g_v);   float* v    = (float*)p;
    cudaGetSymbolAddress(&p, g_y);   float* y    = (float*)p;
    cudaGetSymbolAddress(&p, g_h);   float* h    = (float*)p;
    cudaGetSymbolAddress(&p, g_w);   float* wbuf = (float*)p;
    cudaGetSymbolAddress(&p, g_za);  float* za   = (float*)p;
    cudaGetSymbolAddress(&p, g_zb);  float* zbb  = (float*)p;
    cudaGetSymbolAddress(&p, g_P);   float* P    = (float*)p;
    cudaGetSymbolAddress(&p, g_flag); int* flag  = (int*)p;
    cudaGetSymbolAddress(&p, g_Ah);  __half* Ahp = (__half*)p;
    cudaGetSymbolAddress(&p, g_Al);  __half* Alp = (__half*)p;
    cudaGetSymbolAddress(&p, g_Gh);  __half* Ghp = (__half*)p;
    cudaGetSymbolAddress(&p, g_Gl);  __half* Glp = (__half*)p;
    cudaGetSymbolAddress(&p, g_uh);  __half* uhp = (__half*)p;
    cudaGetSymbolAddress(&p, g_ul);  __half* ulp = (__half*)p;
    cudaGetSymbolAddress(&p, g_rth); __half* rthp = (__half*)p;
    cudaGetSymbolAddress(&p, g_rtl); __half* rtlp = (__half*)p;
    cudaGetSymbolAddress(&p, g_Sh);  __half* Shp = (__half*)p;
    cudaGetSymbolAddress(&p, g_Sl);  __half* Slp = (__half*)p;
    cudaGetSymbolAddress(&p, g_Xh);  __half* Xhp = (__half*)p;
    cudaGetSymbolAddress(&p, g_Xl);  __half* Xlp = (__half*)p;
    cudaGetSymbolAddress(&p, g_Th);  __half* Thp = (__half*)p;
    cudaGetSymbolAddress(&p, g_Tl);  __half* Tlp = (__half*)p;
    cudaGetSymbolAddress(&p, g_dh);  __half* dhp = (__half*)p;
    cudaGetSymbolAddress(&p, g_dl);  __half* dlp = (__half*)p;
    cudaGetSymbolAddress(&p, g_W1h); __half* W1h = (__half*)p;
    cudaGetSymbolAddress(&p, g_W1l); __half* W1l = (__half*)p;
    cudaGetSymbolAddress(&p, g_W2h); __half* W2h = (__half*)p;
    cudaGetSymbolAddress(&p, g_W2l); __half* W2l = (__half*)p;
    cudaGetSymbolAddress(&p, g_hph); __half* hph = (__half*)p;
    cudaGetSymbolAddress(&p, g_hpl); __half* hpl = (__half*)p;

    cudaFuncSetAttribute(hgemm_k<3, EPI_NONE>,
                         cudaFuncAttributeMaxDynamicSharedMemorySize, HSMEM);
    cudaFuncSetAttribute(hgemm_k<1, EPI_NONE>,
                         cudaFuncAttributeMaxDynamicSharedMemorySize, HSMEM);
    cudaFuncSetAttribute(hgemm_k<3, EPI_RT>,
                         cudaFuncAttributeMaxDynamicSharedMemorySize, HSMEM);
    cudaFuncSetAttribute(hgemm_k<3, EPI_Z>,
                         cudaFuncAttributeMaxDynamicSharedMemorySize, HSMEM);
    cudaFuncSetAttribute(hgemm_k<3, EPI_ZFIN>,
                         cudaFuncAttributeMaxDynamicSharedMemorySize, HSMEM);

    init_k<<<1, 1>>>();
    copy4_k<<<(BC * N2C / 4) / 256, 256>>>((float4*)za, (const float4*)dz0);

    // A planes (x64)
    splitH_k<<<(int)(((size_t)N1C * N2C / 8) / 256), 256>>>(dA, Ahp, Alp, A_SC);

    // S = A A^T : accum = 4096*S, split 4
    {
        dim3 g(N1C / 128, N1C / 128, SPL_S);
        hgemm_k<3, EPI_NONE><<<g, 256, HSMEM>>>(Ahp, Alp, N2C, Ahp, Alp, N2C, P, N1C,
            N2C / SPL_S, nullptr, nullptr, nullptr, nullptr, nullptr);
        reduce_sum_k<<<(N1C * N1C / 8) / 256, 256>>>(P, S, (size_t)N1C * N1C / 4, SPL_S, 1.f / 4096.f);
    }

    // power iteration (fp32 S)
    fill_k<<<N1C / 256, 256>>>(v, 0.03125f, N1C);
    for (int i = 0; i < PI_ITERS; i++) {
        spmv_k<<<N1C / 8, dim3(32, 8)>>>(S, v, y);
        pi_norm_k<<<1, 256>>>(y, v);
    }
    initX_k<<<(N1C * N1C) / 256, 256>>>(Xa);

    // S planes (x16)
    splitH_k<<<(int)(((size_t)N1C * N1C / 8) / 256), 256>>>(S, Shp, Slp, 16.f);

    // Newton-Schulz: 4 cheap + 2 precise, symmetrized, split 4
    float* Xc = Xa; float* Xn = Xb;
    {
        dim3 g(N1C / 128, N1C / 128, SPL_NS);
        dim3 gsym(N1C / 32, N1C / 8);
        size_t s4 = (size_t)N1C * N1C / 4;
        int nsgrid = (N1C * N1C / 8) / 256;
        for (int i = 0; i < NS_ITERS; i++) {
            symm_k<<<gsym, 256>>>(Xc);
            splitH_k<<<(N1C * N1C / 8) / 256, 256>>>(Xc, Xhp, Xlp, 32.f);
            if (i < NS_CHEAP)
                hgemm_k<1, EPI_NONE><<<g, 256, HSMEM>>>(Xhp, Xlp, N1C, Shp, Slp, N1C, P, N1C,
                    N1C / SPL_NS, nullptr, nullptr, nullptr, nullptr, nullptr);
            else
                hgemm_k<3, EPI_NONE><<<g, 256, HSMEM>>>(Xhp, Xlp, N1C, Shp, Slp, N1C, P, N1C,
                    N1C / SPL_NS, nullptr, nullptr, nullptr, nullptr, nullptr);
            reduce_sum_k<<<nsgrid, 256>>>(P, Tm, s4, SPL_NS, 1.f / 512.f);
            splitH_k<<<(N1C * N1C / 8) / 256, 256>>>(Tm, Thp, Tlp, 32.f);
            if (i < NS_CHEAP)
                hgemm_k<1, EPI_NONE><<<g, 256, HSMEM>>>(Thp, Tlp, N1C, Xhp, Xlp, N1C, P, N1C,
                    N1C / SPL_NS, nullptr, nullptr, nullptr, nullptr, nullptr);
            else
                hgemm_k<3, EPI_NONE><<<g, 256, HSMEM>>>(Thp, Tlp, N1C, Xhp, Xlp, N1C, P, N1C,
                    N1C / SPL_NS, nullptr, nullptr, nullptr, nullptr, nullptr);
            reduce_ns_k<<<nsgrid, 256>>>(P, Xc, Xn, s4, SPL_NS, 1.f / 1024.f);
            float* t2 = Xc; Xc = Xn; Xn = t2;
        }
        symm_k<<<gsym, 256>>>(Xc);
    }

    // c = A^T (X b)
    spmv_k<<<N1C / 8, dim3(32, 8)>>>(Xc, dB, tv);
    atmv_k<<<N2C / 256, 256>>>(dA, tv, c);

    // G = A^T X
    transp_k<<<dim3(N2C / 32, N1C / 32), dim3(32, 8)>>>(At, dA, N1C, N2C);
    splitH_k<<<(int)(((size_t)N2C * N1C / 8) / 256), 256>>>(At, Ghp, Glp, A_SC);
    splitH_k<<<(N1C * N1C / 8) / 256, 256>>>(Xc, Xhp, Xlp, 32.f);
    {
        dim3 g(N1C / 128, N2C / 128, 1);
        hgemm_k<3, EPI_NONE><<<g, 256, HSMEM>>>(Ghp, Glp, N1C, Xhp, Xlp, N1C, P, N1C,
            N1C, nullptr, nullptr, nullptr, nullptr, nullptr);
        reduce_sum_k<<<(int)(((size_t)N2C * N1C / 8) / 256), 256>>>(
            P, G, 0, 1, 1.f / 2048.f);
    }
    splitH_k<<<(int)(((size_t)N2C * N1C / 8) / 256), 256>>>(G, Ghp, Glp, G_SC);

    // MLP
    transp_k<<<dim3(HC / 32, DC / 32), dim3(32, 8)>>>(W1t, dW1, DC, HC);
    splitH_k<<<(int)(((size_t)HC * DC / 8) / 256), 256>>>(W1t, W1h, W1l, 32.f);
    transp_k<<<dim3(N2C / 32, HC / 32), dim3(32, 8)>>>(W2t, dW2, HC, N2C);
    splitH_k<<<(int)(((size_t)N2C * HC / 8) / 256), 256>>>(W2t, W2h, W2l, 32.f);
    splitH_k<<<(BC * DC / 8) / 256, 256>>>(dd, dhp, dlp, 1.f);
    {
        dim3 g1(HC / 128, BC / 128, SPL_M1);
        hgemm_k<3, EPI_NONE><<<g1, 256, HSMEM>>>(dhp, dlp, DC, W1h, W1l, DC, P, HC,
            DC / SPL_M1, nullptr, nullptr, nullptr, nullptr, nullptr);
        reduce_bias_k<true><<<(BC * HC / 8) / 256, 256>>>(
            P, db1, h, (size_t)BC * HC / 4, SPL_M1, HC / 4, 1.f / 32.f);
        splitH_k<<<(BC * HC / 8) / 256, 256>>>(h, hph, hpl, 1.f);
        dim3 g2(N2C / 128, BC / 128, SPL_M2);
        hgemm_k<3, EPI_NONE><<<g2, 256, HSMEM>>>(hph, hpl, HC, W2h, W2l, HC, P, N2C,
            HC / SPL_M2, nullptr, nullptr, nullptr, nullptr, nullptr);
        reduce_bias_k<false><<<(BC * N2C / 8) / 256, 256>>>(
            P, db2, wbuf, (size_t)BC * N2C / 4, SPL_M2, N2C / 4, 1.f / 32.f);
    }

    // initial u planes
    u0_k<<<(BC * N2C / 4) / 256, 256>>>(za, wbuf);

    // DYS loop: 2 fused kernels per iteration
    dim3 gr(N1C / 128, BC / 128, SPL_GR);    // rt = u A^T (M=256,N=1024), tail->rt planes
    dim3 gz(N2C / 128, BC / 128, SPL_GZ);    // 32*(G r)^T, tail->z update
    float* zb2[2] = { za, zbb };
    for (int it = 1; it <= 50; ++it) {
        const float* zin = zb2[(it - 1) & 1];
        float* zout = zb2[it & 1];
        hgemm_k<3, EPI_RT><<<gr, 256, HSMEM>>>(uhp, ulp, N2C, Ahp, Alp, N2C, P, N1C,
            N2C / SPL_GR, flag, nullptr, nullptr, nullptr, nullptr);
        hgemm_k<3, EPI_Z><<<gz, 256, HSMEM>>>(rthp, rtlp, N1C, Ghp, Glp, N1C, P, N2C,
            N1C / SPL_GZ, flag, zin, wbuf, c, zout);
    }

    // final unguarded step, relu into d_out
    hgemm_k<3, EPI_RT><<<gr, 256, HSMEM>>>(uhp, ulp, N2C, Ahp, Alp, N2C, P, N1C,
        N2C / SPL_GR, nullptr, nullptr, nullptr, nullptr, nullptr);
    hgemm_k<3, EPI_ZFIN><<<gz, 256, HSMEM>>>(rthp, rtlp, N1C, Ghp, Glp, N1C, P, N2C,
        N1C / SPL_GZ, nullptr, za, wbuf, c, out);
}

// round 16
// speedup vs baseline: 1.1715x; 1.1715x over previous
#include <cuda_runtime.h>
#include <cuda_fp16.h>
#include <math.h>
#include <stdint.h>

// ----------------------------------------------------------------------------
// DYS_opt_net.  ALL GEMMs on legacy fp16 mma.sync m16n8k16 with fp16x3 split
// (hh+hl+lh, fp32 accum), static per-matrix scaling, symmetrized Newton-Schulz
// (4 cheap + 2 precise), 2-stage cp.async, 2 CTAs/SM, per-row LDSM interleave.
// R16: revert R15 fusion regression; keep operand-swapped loop GEMM1
// (rt = u A^T directly) + plain vectorized reduce (no smem transpose).
// z' = relu(z) - a*w + c - (G (A u^T))^T,  u = |z| - a*w
// ----------------------------------------------------------------------------

#define N1C 1024
#define N2C 4096
#define BC  256
#define DC  512
#define HC  2048

#define ALPHA_C 0.05f
#define EPS_C   0.01f
#define NS_ITERS 6
#define NS_CHEAP 4
#define PI_ITERS 12

#define A_SC 64.f
#define G_SC 32.f
#define INV_A_SC 0.015625f
#define INV_G_SC 0.03125f

#define SPL_GR 16
#define SPL_GZ 4
#define SPL_S  4
#define SPL_NS 4
#define SPL_M1 8
#define SPL_M2 4

// fp16 GEMM tile config
#define HBK 32
#define HSTR 40
#define HPL (128*HSTR)
#define HST (4*HPL)
#define HSMEM (2*HST*2)          // 81920 B -> 2 CTAs/SM

__device__ float g_S  [(size_t)N1C*N1C];
__device__ float g_Xa [(size_t)N1C*N1C];
__device__ float g_Xb [(size_t)N1C*N1C];
__device__ float g_T  [(size_t)N1C*N1C];
__device__ float g_G  [(size_t)N2C*N1C];
__device__ float g_At [(size_t)N2C*N1C];
__device__ float g_W1t[(size_t)HC*DC];
__device__ float g_W2t[(size_t)N2C*HC];
__device__ float g_c  [N2C];
__device__ float g_tv [N1C];
__device__ float g_v  [N1C];
__device__ float g_y  [N1C];
__device__ float g_h  [(size_t)BC*HC];
__device__ float g_w  [(size_t)BC*N2C];
__device__ float g_za [(size_t)BC*N2C];
__device__ float g_zb [(size_t)BC*N2C];
__device__ float g_P  [(size_t)4*1024*1024];
__device__ __half g_Ah [(size_t)N1C*N2C];
__device__ __half g_Al [(size_t)N1C*N2C];
__device__ __half g_Gh [(size_t)N2C*N1C];
__device__ __half g_Gl [(size_t)N2C*N1C];
__device__ __half g_uh [(size_t)BC*N2C];
__device__ __half g_ul [(size_t)BC*N2C];
__device__ __half g_rth[(size_t)BC*N1C];
__device__ __half g_rtl[(size_t)BC*N1C];
__device__ __half g_Sh [(size_t)N1C*N1C];
__device__ __half g_Sl [(size_t)N1C*N1C];
__device__ __half g_Xh [(size_t)N1C*N1C];
__device__ __half g_Xl [(size_t)N1C*N1C];
__device__ __half g_Th [(size_t)N1C*N1C];
__device__ __half g_Tl [(size_t)N1C*N1C];
__device__ __half g_dh [(size_t)BC*DC];
__device__ __half g_dl [(size_t)BC*DC];
__device__ __half g_W1h[(size_t)HC*DC];
__device__ __half g_W1l[(size_t)HC*DC];
__device__ __half g_W2h[(size_t)N2C*HC];
__device__ __half g_W2l[(size_t)N2C*HC];
__device__ __half g_hph[(size_t)BC*HC];
__device__ __half g_hpl[(size_t)BC*HC];
__device__ float g_lam;
__device__ float g_ss;
__device__ int   g_flag;
__device__ int   g_cnt;

// ---------------- small utility kernels ----------------
__global__ void init_k() { g_ss = 0.f; g_flag = 0; g_cnt = 0; }

__global__ void copy4_k(float4* __restrict__ dst, const float4* __restrict__ src) {
    int i = blockIdx.x * blockDim.x + threadIdx.x;
    dst[i] = src[i];
}

__global__ void fill_k(float* v, float val, int n) {
    int i = blockIdx.x * blockDim.x + threadIdx.x;
    if (i < n) v[i] = val;
}

__global__ void symm_k(float* __restrict__ X) {
    int j = blockIdx.x * 32 + (threadIdx.x & 31);
    int i = blockIdx.y * 8 + (threadIdx.x >> 5);
    if (i < j) {
        size_t ij = (size_t)i * N1C + j;
        size_t ji = (size_t)j * N1C + i;
        float m = 0.5f * (X[ij] + X[ji]);
        X[ij] = m;
        X[ji] = m;
    }
}

__global__ void spmv_k(const float* __restrict__ M_, const float* __restrict__ v,
                       float* __restrict__ y) {
    int row = blockIdx.x * 8 + threadIdx.y;
    const float* mr = M_ + (size_t)row * N1C;
    float s = 0.f;
    for (int j = threadIdx.x; j < N1C; j += 32) s += mr[j] * v[j];
    #pragma unroll
    for (int o = 16; o; o >>= 1) s += __shfl_xor_sync(0xffffffffu, s, o);
    if (threadIdx.x == 0) y[row] = s;
}

__global__ void pi_norm_k(const float* __restrict__ y, float* __restrict__ v) {
    __shared__ float red[256];
    float s = 0.f;
    for (int i = threadIdx.x; i < N1C; i += 256) { float t = y[i]; s += t * t; }
    red[threadIdx.x] = s; __syncthreads();
    for (int o = 128; o; o >>= 1) {
        if (threadIdx.x < o) red[threadIdx.x] += red[threadIdx.x + o];
        __syncthreads();
    }
    float nrm = sqrtf(red[0]);
    float inv = 1.f / nrm;
    for (int i = threadIdx.x; i < N1C; i += 256) v[i] = y[i] * inv;
    if (threadIdx.x == 0) g_lam = nrm;
}

__global__ void initX_k(float* X) {
    float a = 1.8f / g_lam;
    int i = blockIdx.x * 256 + threadIdx.x;
    int rr = i / N1C, cc = i % N1C;
    X[i] = (rr == cc) ? a : 0.f;
}

__global__ void atmv_k(const float* __restrict__ A, const float* __restrict__ t,
                       float* __restrict__ c) {
    __shared__ float ts[N1C];
    for (int i = threadIdx.x; i < N1C; i += 256) ts[i] = t[i];
    __syncthreads();
    int j = blockIdx.x * 256 + threadIdx.x;
    float s = 0.f;
    for (int i = 0; i < N1C; i++) s += A[(size_t)i * N2C + j] * ts[i];
    c[j] = s;
}

__global__ void transp_k(float* __restrict__ dst, const float* __restrict__ src,
                         int R, int C) {
    __shared__ float t[32][33];
    int bx = blockIdx.x * 32, by = blockIdx.y * 32;
    #pragma unroll
    for (int i = 0; i < 4; i++) {
        int r = by + threadIdx.y + i * 8;
        t[threadIdx.y + i * 8][threadIdx.x] = src[(size_t)r * C + bx + threadIdx.x];
    }
    __syncthreads();
    #pragma unroll
    for (int i = 0; i < 4; i++) {
        int r = bx + threadIdx.y + i * 8;
        dst[(size_t)r * R + by + threadIdx.x] = t[threadIdx.x][threadIdx.y + i * 8];
    }
}

__device__ __forceinline__ void split2h(float x, __half& h, __half& l) {
    h = __float2half_rn(x);
    l = __float2half_rn(x - __half2float(h));
}

__global__ void splitH_k(const float* __restrict__ src, __half* __restrict__ ph,
                         __half* __restrict__ pl, float scale) {
    size_t e = ((size_t)blockIdx.x * 256 + threadIdx.x) * 8;
    uint32_t hh[4], ll[4];
    #pragma unroll
    for (int p = 0; p < 4; p++) {
        __half h0, h1, l0, l1;
        split2h(src[e + 2 * p] * scale, h0, l0);
        split2h(src[e + 2 * p + 1] * scale, h1, l1);
        __half2 hp = __halves2half2(h0, h1), lp = __halves2half2(l0, l1);
        hh[p] = *(uint32_t*)&hp; ll[p] = *(uint32_t*)&lp;
    }
    *(uint4*)(ph + e) = make_uint4(hh[0], hh[1], hh[2], hh[3]);
    *(uint4*)(pl + e) = make_uint4(ll[0], ll[1], ll[2], ll[3]);
}

__global__ void u0_k(const float* __restrict__ z, const float* __restrict__ w) {
    size_t i = (size_t)blockIdx.x * 256 + threadIdx.x;
    float4 zv = ((const float4*)z)[i];
    float4 wv = ((const float4*)w)[i];
    __half h0, h1, h2, h3, l0, l1, l2, l3;
    split2h(fabsf(zv.x) - ALPHA_C * wv.x, h0, l0);
    split2h(fabsf(zv.y) - ALPHA_C * wv.y, h1, l1);
    split2h(fabsf(zv.z) - ALPHA_C * wv.z, h2, l2);
    split2h(fabsf(zv.w) - ALPHA_C * wv.w, h3, l3);
    __half2 ha = __halves2half2(h0, h1), hb = __halves2half2(h2, h3);
    __half2 la = __halves2half2(l0, l1), lb = __halves2half2(l2, l3);
    ((uint2*)g_uh)[i] = make_uint2(*(uint32_t*)&ha, *(uint32_t*)&hb);
    ((uint2*)g_ul)[i] = make_uint2(*(uint32_t*)&la, *(uint32_t*)&lb);
}

// ---------------- reduce kernels (2x float4 ILP, scaled) ----------------
__global__ void reduce_sum_k(const float* __restrict__ P, float* __restrict__ out,
                             size_t stride4, int ns, float scale) {
    size_t i = ((size_t)blockIdx.x * 256 + threadIdx.x) * 2;
    const float4* p = (const float4*)P;
    float4 s0 = p[i], s1 = p[i + 1];
    for (int sp = 1; sp < ns; sp++) {
        float4 t0 = p[(size_t)sp * stride4 + i];
        float4 t1 = p[(size_t)sp * stride4 + i + 1];
        s0.x += t0.x; s0.y += t0.y; s0.z += t0.z; s0.w += t0.w;
        s1.x += t1.x; s1.y += t1.y; s1.z += t1.z; s1.w += t1.w;
    }
    s0.x *= scale; s0.y *= scale; s0.z *= scale; s0.w *= scale;
    s1.x *= scale; s1.y *= scale; s1.z *= scale; s1.w *= scale;
    ((float4*)out)[i] = s0;
    ((float4*)out)[i + 1] = s1;
}

__global__ void reduce_ns_k(const float* __restrict__ P, const float* __restrict__ X,
                            float* __restrict__ out, size_t stride4, int ns, float scale) {
    size_t i = ((size_t)blockIdx.x * 256 + threadIdx.x) * 2;
    const float4* p = (const float4*)P;
    float4 s0 = p[i], s1 = p[i + 1];
    for (int sp = 1; sp < ns; sp++) {
        float4 t0 = p[(size_t)sp * stride4 + i];
        float4 t1 = p[(size_t)sp * stride4 + i + 1];
        s0.x += t0.x; s0.y += t0.y; s0.z += t0.z; s0.w += t0.w;
        s1.x += t1.x; s1.y += t1.y; s1.z += t1.z; s1.w += t1.w;
    }
    float4 x0 = ((const float4*)X)[i], x1 = ((const float4*)X)[i + 1];
    float4 o0, o1;
    o0.x = 2.f * x0.x - s0.x * scale; o0.y = 2.f * x0.y - s0.y * scale;
    o0.z = 2.f * x0.z - s0.z * scale; o0.w = 2.f * x0.w - s0.w * scale;
    o1.x = 2.f * x1.x - s1.x * scale; o1.y = 2.f * x1.y - s1.y * scale;
    o1.z = 2.f * x1.z - s1.z * scale; o1.w = 2.f * x1.w - s1.w * scale;
    ((float4*)out)[i] = o0;
    ((float4*)out)[i + 1] = o1;
}

template<bool RELU>
__global__ void reduce_bias_k(const float* __restrict__ P, const float* __restrict__ bias,
                              float* __restrict__ out, size_t stride4, int ns, int n4,
                              float scale) {
    size_t i = ((size_t)blockIdx.x * 256 + threadIdx.x) * 2;
    const float4* p = (const float4*)P;
    float4 s0 = p[i], s1 = p[i + 1];
    for (int sp = 1; sp < ns; sp++) {
        float4 t0 = p[(size_t)sp * stride4 + i];
        float4 t1 = p[(size_t)sp * stride4 + i + 1];
        s0.x += t0.x; s0.y += t0.y; s0.z += t0.z; s0.w += t0.w;
        s1.x += t1.x; s1.y += t1.y; s1.z += t1.z; s1.w += t1.w;
    }
    float4 b0 = ((const float4*)bias)[i % n4];
    float4 b1 = ((const float4*)bias)[(i + 1) % n4];
    s0.x = s0.x * scale + b0.x; s0.y = s0.y * scale + b0.y;
    s0.z = s0.z * scale + b0.z; s0.w = s0.w * scale + b0.w;
    s1.x = s1.x * scale + b1.x; s1.y = s1.y * scale + b1.y;
    s1.z = s1.z * scale + b1.z; s1.w = s1.w * scale + b1.w;
    if (RELU) {
        s0.x = fmaxf(s0.x, 0.f); s0.y = fmaxf(s0.y, 0.f);
        s0.z = fmaxf(s0.z, 0.f); s0.w = fmaxf(s0.w, 0.f);
        s1.x = fmaxf(s1.x, 0.f); s1.y = fmaxf(s1.y, 0.f);
        s1.z = fmaxf(s1.z, 0.f); s1.w = fmaxf(s1.w, 0.f);
    }
    ((float4*)out)[i] = s0;
    ((float4*)out)[i + 1] = s1;
}

// sum SPL_GR partials of 64*rt [BC][N1C]; scale 1/64; split to rt planes.
// Fully coalesced: each thread handles 8 contiguous elements.
__global__ void reduce_rt_k(const float* __restrict__ P, const int* __restrict__ guard) {
    if (guard && *guard) return;
    size_t i = ((size_t)blockIdx.x * 256 + threadIdx.x) * 2;   // float4 index
    const float4* p = (const float4*)P;
    const size_t s4 = (size_t)BC * N1C / 4;
    float4 s0 = p[i], s1 = p[i + 1];
    #pragma unroll
    for (int sp = 1; sp < SPL_GR; sp++) {
        float4 t0 = p[(size_t)sp * s4 + i];
        float4 t1 = p[(size_t)sp * s4 + i + 1];
        s0.x += t0.x; s0.y += t0.y; s0.z += t0.z; s0.w += t0.w;
        s1.x += t1.x; s1.y += t1.y; s1.z += t1.z; s1.w += t1.w;
    }
    float v[8] = { s0.x * INV_A_SC, s0.y * INV_A_SC, s0.z * INV_A_SC, s0.w * INV_A_SC,
                   s1.x * INV_A_SC, s1.y * INV_A_SC, s1.z * INV_A_SC, s1.w * INV_A_SC };
    uint32_t hh[4], ll[4];
    #pragma unroll
    for (int q = 0; q < 4; q++) {
        __half h0, h1, l0, l1;
        split2h(v[2 * q], h0, l0);
        split2h(v[2 * q + 1], h1, l1);
        __half2 hp = __halves2half2(h0, h1), lp = __halves2half2(l0, l1);
        hh[q] = *(uint32_t*)&hp; ll[q] = *(uint32_t*)&lp;
    }
    size_t e = i * 4;
    *(uint4*)(g_rth + e) = make_uint4(hh[0], hh[1], hh[2], hh[3]);
    *(uint4*)(g_rtl + e) = make_uint4(ll[0], ll[1], ll[2], ll[3]);
}

// z-update: zn = relu(z) - a*w + c - (1/32)*sum(SPL_GZ partials); + u planes + check
template<bool FIN>
__global__ void zupd_k(const float* __restrict__ P, const float* __restrict__ zin,
                       const float* __restrict__ w, const float* __restrict__ c,
                       float* __restrict__ zout, const int* __restrict__ guard) {
    size_t gid = (size_t)blockIdx.x * 256 + threadIdx.x;
    size_t i = gid * 2;
    if (!FIN && guard && *guard) {
        ((float4*)zout)[i] = ((const float4*)zin)[i];
        ((float4*)zout)[i + 1] = ((const float4*)zin)[i + 1];
        return;
    }
    const float4* p = (const float4*)P;
    float ov[8], wv8[8];
    float ls = 0.f;
    #pragma unroll
    for (int q = 0; q < 2; q++) {
        float4 s = p[i + q];
        #pragma unroll
        for (int sp = 1; sp < SPL_GZ; sp++) {
            float4 t = p[(size_t)sp * (BC * (N2C / 4)) + i + q];
            s.x += t.x; s.y += t.y; s.z += t.z; s.w += t.w;
        }
        float4 z = ((const float4*)zin)[i + q];
        float4 ww = ((const float4*)w)[i + q];
        float4 cc = ((const float4*)c)[(i + q) & (N2C / 4 - 1)];
        float4 o;
        o.x = fmaxf(z.x, 0.f) - ALPHA_C * ww.x + cc.x - s.x * INV_G_SC;
        o.y = fmaxf(z.y, 0.f) - ALPHA_C * ww.y + cc.y - s.y * INV_G_SC;
        o.z = fmaxf(z.z, 0.f) - ALPHA_C * ww.z + cc.z - s.z * INV_G_SC;
        o.w = fmaxf(z.w, 0.f) - ALPHA_C * ww.w + cc.w - s.w * INV_G_SC;
        if (FIN) {
            o.x = fmaxf(o.x, 0.f); o.y = fmaxf(o.y, 0.f);
            o.z = fmaxf(o.z, 0.f); o.w = fmaxf(o.w, 0.f);
            ((float4*)zout)[i + q] = o;
        } else {
            ((float4*)zout)[i + q] = o;
            float dx = o.x - z.x, dy = o.y - z.y, dz = o.z - z.z, dw = o.w - z.w;
            ls += dx * dx + dy * dy + dz * dz + dw * dw;
            ov[q * 4 + 0] = o.x; ov[q * 4 + 1] = o.y;
            ov[q * 4 + 2] = o.z; ov[q * 4 + 3] = o.w;
            wv8[q * 4 + 0] = ww.x; wv8[q * 4 + 1] = ww.y;
            wv8[q * 4 + 2] = ww.z; wv8[q * 4 + 3] = ww.w;
        }
    }
    if (!FIN) {
        uint32_t hh[4], ll[4];
        #pragma unroll
        for (int pq = 0; pq < 4; pq++) {
            __half h0, h1, l0, l1;
            split2h(fabsf(ov[2 * pq]) - ALPHA_C * wv8[2 * pq], h0, l0);
            split2h(fabsf(ov[2 * pq + 1]) - ALPHA_C * wv8[2 * pq + 1], h1, l1);
            __half2 hp = __halves2half2(h0, h1), lp = __halves2half2(l0, l1);
            hh[pq] = *(uint32_t*)&hp; ll[pq] = *(uint32_t*)&lp;
        }
        size_t e = gid * 8;
        *(uint4*)(g_uh + e) = make_uint4(hh[0], hh[1], hh[2], hh[3]);
        *(uint4*)(g_ul + e) = make_uint4(ll[0], ll[1], ll[2], ll[3]);

        __shared__ float red[256];
        red[threadIdx.x] = ls;
        __syncthreads();
        for (int o2 = 128; o2; o2 >>= 1) {
            if (threadIdx.x < o2) red[threadIdx.x] += red[threadIdx.x + o2];
            __syncthreads();
        }
        if (threadIdx.x == 0) {
            atomicAdd(&g_ss, red[0]);
            __threadfence();
            int t = atomicAdd(&g_cnt, 1);
            if (t == (int)gridDim.x - 1) {
                if (g_ss <= EPS_C * EPS_C) g_flag = 1;
                g_ss = 0.f;
                g_cnt = 0;
            }
        }
    }
}

// ---------------- fp16 GEMM (NP=3: hh+hl+lh; NP=1: hh only) ----------------
__device__ __forceinline__ uint32_t smem_u32(const void* p) {
    uint32_t a;
    asm("{ .reg .u64 t; cvta.to.shared.u64 t, %1; cvt.u32.u64 %0, t; }" : "=r"(a) : "l"(p));
    return a;
}
__device__ __forceinline__ void cp16(uint32_t dst, const void* src) {
    asm volatile("cp.async.cg.shared.global [%0], [%1], 16;" :: "r"(dst), "l"(src));
}
__device__ __forceinline__ void ldsm4(uint32_t* r, uint32_t a) {
    asm volatile("ldmatrix.sync.aligned.m8n8.x4.shared.b16 {%0,%1,%2,%3}, [%4];"
        : "=r"(r[0]), "=r"(r[1]), "=r"(r[2]), "=r"(r[3]) : "r"(a));
}
__device__ __forceinline__ void mma16(float* c, const uint32_t* a, const uint32_t* b) {
    asm volatile("mma.sync.aligned.m16n8k16.row.col.f32.f16.f16.f32 "
        "{%0,%1,%2,%3}, {%4,%5,%6,%7}, {%8,%9}, {%0,%1,%2,%3};"
        : "+f"(c[0]), "+f"(c[1]), "+f"(c[2]), "+f"(c[3])
        : "r"(a[0]), "r"(a[1]), "r"(a[2]), "r"(a[3]), "r"(b[0]), "r"(b[1]));
}

template<int NP>
__global__ void __launch_bounds__(256)
hgemm_k(const __half* __restrict__ Ahp, const __half* __restrict__ Alp, int lda,
        const __half* __restrict__ Bhp, const __half* __restrict__ Blp, int ldb,
        float* __restrict__ Cg, int N, int kchunk, const int* __restrict__ guard)
{
    if (guard && *guard) return;
    extern __shared__ __half hsm[];
    const int tid = threadIdx.x, lane = tid & 31, wid = tid >> 5;
    const int wm = wid >> 2, wn = wid & 3;
    const int m0 = blockIdx.y * 128, n0 = blockIdx.x * 128;
    const int k0 = blockIdx.z * kchunk;
    const int ST = kchunk / HBK;
    const __half* psrc[4] = { Ahp, Alp, Bhp, Blp };
    uint32_t sbase = smem_u32(hsm);

    auto load = [&](int s) {
        int buf = s & 1;
        int kb = k0 + s * HBK;
        #pragma unroll
        for (int t = 0; t < (NP == 3 ? 8 : 4); t++) {
            int id = t * 256 + tid;
            int pl = (NP == 3) ? (id >> 9) : ((id >> 9) * 2);
            int idx = id & 511;
            int row = idx >> 2, kc = idx & 3;
            int isB = pl >> 1;
            const __half* src = psrc[pl] +
                (size_t)((isB ? n0 : m0) + row) * (isB ? ldb : lda) + kb + kc * 8;
            uint32_t dst = sbase + (uint32_t)(buf * HST + pl * HPL + row * HSTR + kc * 8) * 2;
            cp16(dst, src);
        }
    };

    float acc[4][4][4];
    #pragma unroll
    for (int f = 0; f < 4; f++)
        #pragma unroll
        for (int g = 0; g < 4; g++)
            #pragma unroll
            for (int e = 0; e < 4; e++) acc[f][g][e] = 0.f;

    load(0);
    asm volatile("cp.async.commit_group;");
    load(1);
    asm volatile("cp.async.commit_group;");

    const int offA = (lane & 15) * HSTR + (lane >> 4) * 8;
    const int offB = ((lane & 7) + ((lane >> 4) << 3)) * HSTR + ((lane >> 3) & 1) * 8;

    for (int s = 0; s < ST; s++) {
        asm volatile("cp.async.wait_group 1;");
        __syncthreads();
        uint32_t stg = sbase + (uint32_t)((s & 1) * HST) * 2;
        #pragma unroll
        for (int ks = 0; ks < 2; ks++) {
            uint32_t bH[4][2], bL[4][2];
            #pragma unroll
            for (int gp = 0; gp < 2; gp++) {
                uint32_t r[4];
                uint32_t base = stg + (uint32_t)(2 * HPL + (wn * 32 + gp * 16) * HSTR + ks * 16 + offB) * 2;
                ldsm4(r, base);
                bH[gp * 2][0] = r[0]; bH[gp * 2][1] = r[1];
                bH[gp * 2 + 1][0] = r[2]; bH[gp * 2 + 1][1] = r[3];
                if (NP == 3) {
                    ldsm4(r, base + HPL * 2);
                    bL[gp * 2][0] = r[0]; bL[gp * 2][1] = r[1];
                    bL[gp * 2 + 1][0] = r[2]; bL[gp * 2 + 1][1] = r[3];
                }
            }
            #pragma unroll
            for (int f = 0; f < 4; f++) {
                uint32_t aH[4], aL[4];
                uint32_t base = stg + (uint32_t)((wm * 64 + f * 16) * HSTR + ks * 16 + offA) * 2;
                ldsm4(aH, base);
                if (NP == 3) ldsm4(aL, base + HPL * 2);
                #pragma unroll
                for (int g = 0; g < 4; g++)
                    mma16(acc[f][g], aH, bH[g]);
                if (NP == 3) {
                    #pragma unroll
                    for (int g = 0; g < 4; g++)
                        mma16(acc[f][g], aH, bL[g]);
                    #pragma unroll
                    for (int g = 0; g < 4; g++)
                        mma16(acc[f][g], aL, bH[g]);
                }
            }
        }
        __syncthreads();
        if (s + 2 < ST) load(s + 2);
        asm volatile("cp.async.commit_group;");
    }

    size_t off = (size_t)blockIdx.z * ((size_t)gridDim.y * 128) * N;
    const int tr = lane >> 2, tc = (lane & 3) * 2;
    #pragma unroll
    for (int f = 0; f < 4; f++) {
        int m = m0 + wm * 64 + f * 16 + tr;
        #pragma unroll
        for (int g = 0; g < 4; g++) {
            int n = n0 + wn * 32 + g * 8 + tc;
            *(float2*)&Cg[off + (size_t)m * N + n] = make_float2(acc[f][g][0], acc[f][g][1]);
            *(float2*)&Cg[off + (size_t)(m + 8) * N + n] = make_float2(acc[f][g][2], acc[f][g][3]);
        }
    }
}

// ---------------- host ----------------
extern "C" void kernel_launch(void* const* d_in, const int* in_sizes, int n_in,
                              void* d_out, int out_size) {
    (void)in_sizes; (void)n_in; (void)out_size;
    const float* dd  = (const float*)d_in[0];
    const float* dA  = (const float*)d_in[1];
    const float* dB  = (const float*)d_in[2];
    const float* dW1 = (const float*)d_in[3];
    const float* db1 = (const float*)d_in[4];
    const float* dW2 = (const float*)d_in[5];
    const float* db2 = (const float*)d_in[6];
    const float* dz0 = (const float*)d_in[7];
    float* out = (float*)d_out;

    void* p;
    cudaGetSymbolAddress(&p, g_S);   float* S    = (float*)p;
    cudaGetSymbolAddress(&p, g_Xa);  float* Xa   = (float*)p;
    cudaGetSymbolAddress(&p, g_Xb);  float* Xb   = (float*)p;
    cudaGetSymbolAddress(&p, g_T);   float* Tm   = (float*)p;
    cudaGetSymbolAddress(&p, g_G);   float* G    = (float*)p;
    cudaGetSymbolAddress(&p, g_At);  float* At   = (float*)p;
    cudaGetSymbolAddress(&p, g_W1t); float* W1t  = (float*)p;
    cudaGetSymbolAddress(&p, g_W2t); float* W2t  = (float*)p;
    cudaGetSymbolAddress(&p, g_c);   float* c    = (float*)p;
    cudaGetSymbolAddress(&p, g_tv);  float* tv   = (float*)p;
    cudaGetSymbolAddress(&p, g_v);   float* v    = (float*)p;
    cudaGetSymbolAddress(&p, g_y);   float* y    = (float*)p;
    cudaGetSymbolAddress(&p, g_h);   float* h    = (float*)p;
    cudaGetSymbolAddress(&p, g_w);   float* wbuf = (float*)p;
    cudaGetSymbolAddress(&p, g_za);  float* za   = (float*)p;
    cudaGetSymbolAddress(&p, g_zb);  float* zbb  = (float*)p;
    cudaGetSymbolAddress(&p, g_P);   float* P    = (float*)p;
    cudaGetSymbolAddress(&p, g_flag); int* flag  = (int*)p;
    cudaGetSymbolAddress(&p, g_Ah);  __half* Ahp = (__half*)p;
    cudaGetSymbolAddress(&p, g_Al);  __half* Alp = (__half*)p;
    cudaGetSymbolAddress(&p, g_Gh);  __half* Ghp = (__half*)p;
    cudaGetSymbolAddress(&p, g_Gl);  __half* Glp = (__half*)p;
    cudaGetSymbolAddress(&p, g_uh);  __half* uhp = (__half*)p;
    cudaGetSymbolAddress(&p, g_ul);  __half* ulp = (__half*)p;
    cudaGetSymbolAddress(&p, g_rth); __half* rthp = (__half*)p;
    cudaGetSymbolAddress(&p, g_rtl); __half* rtlp = (__half*)p;
    cudaGetSymbolAddress(&p, g_Sh);  __half* Shp = (__half*)p;
    cudaGetSymbolAddress(&p, g_Sl);  __half* Slp = (__half*)p;
    cudaGetSymbolAddress(&p, g_Xh);  __half* Xhp = (__half*)p;
    cudaGetSymbolAddress(&p, g_Xl);  __half* Xlp = (__half*)p;
    cudaGetSymbolAddress(&p, g_Th);  __half* Thp = (__half*)p;
    cudaGetSymbolAddress(&p, g_Tl);  __half* Tlp = (__half*)p;
    cudaGetSymbolAddress(&p, g_dh);  __half* dhp = (__half*)p;
    cudaGetSymbolAddress(&p, g_dl);  __half* dlp = (__half*)p;
    cudaGetSymbolAddress(&p, g_W1h); __half* W1h = (__half*)p;
    cudaGetSymbolAddress(&p, g_W1l); __half* W1l = (__half*)p;
    cudaGetSymbolAddress(&p, g_W2h); __half* W2h = (__half*)p;
    cudaGetSymbolAddress(&p, g_W2l); __half* W2l = (__half*)p;
    cudaGetSymbolAddress(&p, g_hph); __half* hph = (__half*)p;
    cudaGetSymbolAddress(&p, g_hpl); __half* hpl = (__half*)p;

    cudaFuncSetAttribute(hgemm_k<3>,
                         cudaFuncAttributeMaxDynamicSharedMemorySize, HSMEM);
    cudaFuncSetAttribute(hgemm_k<1>,
                         cudaFuncAttributeMaxDynamicSharedMemorySize, HSMEM);

    init_k<<<1, 1>>>();
    copy4_k<<<(BC * N2C / 4) / 256, 256>>>((float4*)za, (const float4*)dz0);

    // A planes (x64)
    splitH_k<<<(int)(((size_t)N1C * N2C / 8) / 256), 256>>>(dA, Ahp, Alp, A_SC);

    // S = A A^T : accum = 4096*S, split 4
    {
        dim3 g(N1C / 128, N1C / 128, SPL_S);
        hgemm_k<3><<<g, 256, HSMEM>>>(Ahp, Alp, N2C, Ahp, Alp, N2C, P, N1C, N2C / SPL_S, nullptr);
        reduce_sum_k<<<(N1C * N1C / 8) / 256, 256>>>(P, S, (size_t)N1C * N1C / 4, SPL_S, 1.f / 4096.f);
    }

    // power iteration (fp32 S)
    fill_k<<<N1C / 256, 256>>>(v, 0.03125f, N1C);
    for (int i = 0; i < PI_ITERS; i++) {
        spmv_k<<<N1C / 8, dim3(32, 8)>>>(S, v, y);
        pi_norm_k<<<1, 256>>>(y, v);
    }
    initX_k<<<(N1C * N1C) / 256, 256>>>(Xa);

    // S planes (x16)
    splitH_k<<<(int)(((size_t)N1C * N1C / 8) / 256), 256>>>(S, Shp, Slp, 16.f);

    // Newton-Schulz: 4 cheap + 2 precise, symmetrized, split 4
    float* Xc = Xa; float* Xn = Xb;
    {
        dim3 g(N1C / 128, N1C / 128, SPL_NS);
        dim3 gsym(N1C / 32, N1C / 8);
        size_t s4 = (size_t)N1C * N1C / 4;
        int nsgrid = (N1C * N1C / 8) / 256;
        for (int i = 0; i < NS_ITERS; i++) {
            symm_k<<<gsym, 256>>>(Xc);
            splitH_k<<<(N1C * N1C / 8) / 256, 256>>>(Xc, Xhp, Xlp, 32.f);
            if (i < NS_CHEAP)
                hgemm_k<1><<<g, 256, HSMEM>>>(Xhp, Xlp, N1C, Shp, Slp, N1C, P, N1C, N1C / SPL_NS, nullptr);
            else
                hgemm_k<3><<<g, 256, HSMEM>>>(Xhp, Xlp, N1C, Shp, Slp, N1C, P, N1C, N1C / SPL_NS, nullptr);
            reduce_sum_k<<<nsgrid, 256>>>(P, Tm, s4, SPL_NS, 1.f / 512.f);
            splitH_k<<<(N1C * N1C / 8) / 256, 256>>>(Tm, Thp, Tlp, 32.f);
            if (i < NS_CHEAP)
                hgemm_k<1><<<g, 256, HSMEM>>>(Thp, Tlp, N1C, Xhp, Xlp, N1C, P, N1C, N1C / SPL_NS, nullptr);
            else
                hgemm_k<3><<<g, 256, HSMEM>>>(Thp, Tlp, N1C, Xhp, Xlp, N1C, P, N1C, N1C / SPL_NS, nullptr);
            reduce_ns_k<<<nsgrid, 256>>>(P, Xc, Xn, s4, SPL_NS, 1.f / 1024.f);
            float* t2 = Xc; Xc = Xn; Xn = t2;
        }
        symm_k<<<gsym, 256>>>(Xc);
    }

    // c = A^T (X b)
    spmv_k<<<N1C / 8, dim3(32, 8)>>>(Xc, dB, tv);
    atmv_k<<<N2C / 256, 256>>>(dA, tv, c);

    // G = A^T X
    transp_k<<<dim3(N2C / 32, N1C / 32), dim3(32, 8)>>>(At, dA, N1C, N2C);
    splitH_k<<<(int)(((size_t)N2C * N1C / 8) / 256), 256>>>(At, Ghp, Glp, A_SC);
    splitH_k<<<(N1C * N1C / 8) / 256, 256>>>(Xc, Xhp, Xlp, 32.f);
    {
        dim3 g(N1C / 128, N2C / 128, 1);
        hgemm_k<3><<<g, 256, HSMEM>>>(Ghp, Glp, N1C, Xhp, Xlp, N1C, P, N1C, N1C, nullptr);
        reduce_sum_k<<<(int)(((size_t)N2C * N1C / 8) / 256), 256>>>(
            P, G, 0, 1, 1.f / 2048.f);
    }
    splitH_k<<<(int)(((size_t)N2C * N1C / 8) / 256), 256>>>(G, Ghp, Glp, G_SC);

    // MLP
    transp_k<<<dim3(HC / 32, DC / 32), dim3(32, 8)>>>(W1t, dW1, DC, HC);
    splitH_k<<<(int)(((size_t)HC * DC / 8) / 256), 256>>>(W1t, W1h, W1l, 32.f);
    transp_k<<<dim3(N2C / 32, HC / 32), dim3(32, 8)>>>(W2t, dW2, HC, N2C);
    splitH_k<<<(int)(((size_t)N2C * HC / 8) / 256), 256>>>(W2t, W2h, W2l, 32.f);
    splitH_k<<<(BC * DC / 8) / 256, 256>>>(dd, dhp, dlp, 1.f);
    {
        dim3 g1(HC / 128, BC / 128, SPL_M1);
        hgemm_k<3><<<g1, 256, HSMEM>>>(dhp, dlp, DC, W1h, W1l, DC, P, HC, DC / SPL_M1, nullptr);
        reduce_bias_k<true><<<(BC * HC / 8) / 256, 256>>>(
            P, db1, h, (size_t)BC * HC / 4, SPL_M1, HC / 4, 1.f / 32.f);
        splitH_k<<<(BC * HC / 8) / 256, 256>>>(h, hph, hpl, 1.f);
        dim3 g2(N2C / 128, BC / 128, SPL_M2);
        hgemm_k<3><<<g2, 256, HSMEM>>>(hph, hpl, HC, W2h, W2l, HC, P, N2C, HC / SPL_M2, nullptr);
        reduce_bias_k<false><<<(BC * N2C / 8) / 256, 256>>>(
            P, db2, wbuf, (size_t)BC * N2C / 4, SPL_M2, N2C / 4, 1.f / 32.f);
    }

    // initial u planes
    u0_k<<<(BC * N2C / 4) / 256, 256>>>(za, wbuf);

    // DYS loop: operand-swapped GEMM1 outputs rt directly (no transpose)
    dim3 gr(N1C / 128, BC / 128, SPL_GR);   // rt = u A^T : M=BC, N=N1C
    dim3 gz(N2C / 128, BC / 128, SPL_GZ);
    float* zb2[2] = { za, zbb };
    for (int it = 1; it <= 50; ++it) {
        const float* zin = zb2[(it - 1) & 1];
        float* zout = zb2[it & 1];
        hgemm_k<3><<<gr, 256, HSMEM>>>(uhp, ulp, N2C, Ahp, Alp, N2C, P, N1C, N2C / SPL_GR, flag);
        reduce_rt_k<<<(BC * N1C / 8) / 256, 256>>>(P, flag);
        hgemm_k<3><<<gz, 256, HSMEM>>>(rthp, rtlp, N1C, Ghp, Glp, N1C, P, N2C, N1C / SPL_GZ, flag);
        zupd_k<false><<<(BC * N2C / 8) / 256, 256>>>(P, zin, wbuf, c, zout, flag);
    }

    // final unguarded step, relu into d_out
    hgemm_k<3><<<gr, 256, HSMEM>>>(uhp, ulp, N2C, Ahp, Alp, N2C, P, N1C, N2C / SPL_GR, nullptr);
    reduce_rt_k<<<(BC * N1C / 8) / 256, 256>>>(P, nullptr);
    hgemm_k<3><<<gz, 256, HSMEM>>>(rthp, rtlp, N1C, Ghp, Glp, N1C, P, N2C, N1C / SPL_GZ, nullptr);
    zupd_k<true><<<(BC * N2C / 8) / 256, 256>>>(P, za, wbuf, c, out, nullptr);
}